// round 13
// baseline (speedup 1.0000x reference)
#include <cuda_runtime.h>
#include <cuda_fp16.h>
#include <cstdint>

// ============================================================
// x(16384,128) f32, p(16384,8) f32, W(128,4096) f32, b(4096) f32
// logits[b,n] = sum_f x[b,f]*W[f,n],  n = c*512 + d*64 + r
// out[b, d*64+r] = sum_c p[b,c] * softmax_d(logits[b,c,:,r])
//
// R13: single-term fp16 mma.sync, columns permuted n'=r*64+c*8+d.
// TWO warp-groups (4 warps each, 1 per SMSP) in one CTA, each
// owning half the slabs, own W double-buffer + stage + named
// barrier. Group 0 body: MMA->epilogue. Group 1 body:
// epilogue(prev)->MMA. Opposite order = structural anti-phase:
// tensor pipe (one group) and MUFU/FMA epilogue (other group)
// run concurrently on every SMSP at every instant.
// ============================================================

#define NF 128

// -------- device scratch --------
__device__ __align__(1024) uint8_t g_Wh[32u * 32768];   // [slab*2+kh][256n][8ch][16B]
__device__ __align__(1024) uint8_t g_Xh[128u * 32768];  // [rowblk][128r][16ch][16B]
__device__ __align__(16) float g_biasp[4096];

// -------- smem byte offsets --------
#define SM_XH    0                 // 32768
#define SM_W     32768             // 4 x 32768: (grp*2+buf)
#define SM_BIAS  163840            // 16384
#define SM_STAGE 180224            // 2 x 16384 (per group)
#define SM_P     212992            // 4096
#define SM_TOT   217088

__device__ __forceinline__ uint32_t smem_u32(const void* p) {
    return (uint32_t)__cvta_generic_to_shared(p);
}
__device__ __forceinline__ void cp16(uint32_t dst, const void* src) {
    asm volatile("cp.async.cg.shared.global [%0], [%1], 16;" :: "r"(dst), "l"(src));
}
#define LDSM4(r, a) \
    asm volatile("ldmatrix.sync.aligned.m8n8.x4.shared.b16 {%0,%1,%2,%3}, [%4];" \
        : "=r"((r)[0]), "=r"((r)[1]), "=r"((r)[2]), "=r"((r)[3]) : "r"(a))

__device__ __forceinline__ void mma16816h(float* c, const uint32_t* a,
                                          uint32_t b0, uint32_t b1) {
    asm volatile(
        "mma.sync.aligned.m16n8k16.row.col.f32.f16.f16.f32 "
        "{%0,%1,%2,%3}, {%4,%5,%6,%7}, {%8,%9}, {%0,%1,%2,%3};"
        : "+f"(c[0]), "+f"(c[1]), "+f"(c[2]), "+f"(c[3])
        : "r"(a[0]), "r"(a[1]), "r"(a[2]), "r"(a[3]), "r"(b0), "r"(b1));
}
__device__ __forceinline__ uint32_t pack2h(float a, float b) {
    __half2 h;
    h.x = __float2half_rn(a);
    h.y = __float2half_rn(b);
    return *reinterpret_cast<uint32_t*>(&h);
}
#define BARG(id) asm volatile("bar.sync %0, 128;" :: "r"(id) : "memory")

// ============================================================
// Merged prep (unchanged, validated R10-R12)
// ============================================================
__global__ void prep_kernel(const float* __restrict__ X,
                            const float* __restrict__ W,
                            const float* __restrict__ bias) {
    int idx = blockIdx.x * 256 + threadIdx.x;

    if (idx < 4096) {
        int n = idx;
        int c = n >> 9, d = (n >> 6) & 7, r = n & 63;
        g_biasp[r * 64 + c * 8 + d] = bias[n];
    }

    if (idx < 64 * 4096) {
        int f2 = (idx >> 12) * 2;
        int n  = idx & 4095;
        float w0 = W[(size_t)f2 * 4096 + n];
        float w1 = W[(size_t)(f2 + 1) * 4096 + n];
        int c = n >> 9, d = (n >> 6) & 7, r = n & 63;
        int np = r * 64 + c * 8 + d;
        int slab = np >> 8, nl = np & 255;
        int kh = f2 >> 6, kl = f2 & 63;
        int ch = kl >> 3;
        uint32_t off = (uint32_t)(nl * 128 + (((ch ^ (nl & 7)) & 7) << 4) + (kl & 7) * 2);
        *(uint32_t*)(g_Wh + ((size_t)slab * 2 + kh) * 32768 + off) = pack2h(w0, w1);
    }

    {
        int row = idx >> 6;
        int k2  = (idx & 63) * 2;
        float2 v = *reinterpret_cast<const float2*>(X + (size_t)row * NF + k2);
        int blk = row >> 7, rl = row & 127;
        int ch = k2 >> 3;
        uint32_t off = (uint32_t)(rl * 256 + ((ch ^ (rl & 7)) << 4) + (k2 & 7) * 2);
        *(uint32_t*)(g_Xh + (size_t)blk * 32768 + off) = pack2h(v.x, v.y);
    }
}

// fetch one 128-col x K unit (32 KB = 2 x 16 KB kh blocks)
__device__ __forceinline__ void fetch_unit(uint32_t dst, int slab, int h, int tid128) {
    const uint8_t* b0 = g_Wh + ((size_t)slab * 2 + 0) * 32768 + (size_t)h * 16384;
    const uint8_t* b1 = g_Wh + ((size_t)slab * 2 + 1) * 32768 + (size_t)h * 16384;
    #pragma unroll
    for (int j = 0; j < 8; j++) {
        int r16 = tid128 + j * 128;      // float4 index within 16 KB
        cp16(dst + r16 * 16, b0 + (size_t)r16 * 16);
        cp16(dst + 16384 + r16 * 16, b1 + (size_t)r16 * 16);
    }
    asm volatile("cp.async.commit_group;");
}

__device__ __forceinline__ void mma_unit(float (&acc)[2][16][4], uint32_t wbuf,
                                         const uint32_t (&ah)[8][2][4], int lane) {
    #pragma unroll
    for (int mt = 0; mt < 2; mt++)
        #pragma unroll
        for (int nt = 0; nt < 16; nt++)
            #pragma unroll
            for (int e = 0; e < 4; e++) acc[mt][nt][e] = 0.f;

    const int bnl = (lane & 7) + ((lane >> 4) << 3);
    #pragma unroll
    for (int ks8 = 0; ks8 < 8; ks8++) {
        const int bch = (ks8 & 3) * 2 + ((lane >> 3) & 1);
        #pragma unroll
        for (int g2 = 0; g2 < 8; g2++) {
            uint32_t bh[4];
            int nloc = bnl + g2 * 16;
            uint32_t boff = (uint32_t)((ks8 >> 2) * 16384 + nloc * 128
                                       + (((bch ^ (nloc & 7)) & 7) << 4));
            LDSM4(bh, wbuf + boff);
            #pragma unroll
            for (int mt = 0; mt < 2; mt++) {
                mma16816h(&acc[mt][g2 * 2 + 0][0], ah[ks8][mt], bh[0], bh[1]);
                mma16816h(&acc[mt][g2 * 2 + 1][0], ah[ks8][mt], bh[2], bh[3]);
            }
        }
    }
}

__device__ __forceinline__ void epi_unit(const float (&acc)[2][16][4], int ua, int h,
                                         const float* biasS, const float* psS,
                                         float* stage, int wm, int lane) {
    const int q = lane & 3, rowq = lane >> 2;
    float of[2][2][4];
    #pragma unroll
    for (int mt = 0; mt < 2; mt++)
        #pragma unroll
        for (int rb = 0; rb < 2; rb++)
            #pragma unroll
            for (int e = 0; e < 4; e++) of[mt][rb][e] = 0.f;

    #pragma unroll
    for (int mt = 0; mt < 2; mt++) {
        const int row0 = wm * 32 + mt * 16 + rowq;
        #pragma unroll
        for (int nt = 0; nt < 16; nt++) {
            const int c = nt & 7, rb = nt >> 3;
            float2 bv = *(const float2*)&biasS[ua * 128 + nt * 8 + q * 2];
            float e0 = __expf(acc[mt][nt][0] + bv.x);
            float e1 = __expf(acc[mt][nt][1] + bv.y);
            float e2 = __expf(acc[mt][nt][2] + bv.x);
            float e3 = __expf(acc[mt][nt][3] + bv.y);
            float s0 = e0 + e1, s1 = e2 + e3;
            s0 += __shfl_xor_sync(0xffffffffu, s0, 1);
            s0 += __shfl_xor_sync(0xffffffffu, s0, 2);
            s1 += __shfl_xor_sync(0xffffffffu, s1, 1);
            s1 += __shfl_xor_sync(0xffffffffu, s1, 2);
            float f0 = __fdividef(psS[c * 128 + row0], s0);
            float f1 = __fdividef(psS[c * 128 + row0 + 8], s1);
            of[mt][rb][0] = fmaf(e0, f0, of[mt][rb][0]);
            of[mt][rb][1] = fmaf(e1, f0, of[mt][rb][1]);
            of[mt][rb][2] = fmaf(e2, f1, of[mt][rb][2]);
            of[mt][rb][3] = fmaf(e3, f1, of[mt][rb][3]);
        }
    }

    #pragma unroll
    for (int mt = 0; mt < 2; mt++) {
        const int row0 = wm * 32 + mt * 16 + rowq;
        #pragma unroll
        for (int rb = 0; rb < 2; rb++) {
            const int rl = h * 2 + rb;
            stage[row0 * 32 + (2 * q) * 4 + rl]           = of[mt][rb][0];
            stage[row0 * 32 + (2 * q + 1) * 4 + rl]       = of[mt][rb][1];
            stage[(row0 + 8) * 32 + (2 * q) * 4 + rl]     = of[mt][rb][2];
            stage[(row0 + 8) * 32 + (2 * q + 1) * 4 + rl] = of[mt][rb][3];
        }
    }
}

__device__ __forceinline__ void store_slab(const float* stage, float* out,
                                           int rowbase, int slab, int tid128) {
    #pragma unroll
    for (int w = 0; w < 8; w++) {
        int i = tid128 + w * 128;
        int row = i >> 3, d = i & 7;
        float4 v = *(const float4*)&stage[row * 32 + d * 4];
        *(float4*)&out[(size_t)(rowbase + row) * 512 + d * 64 + slab * 4] = v;
    }
}

// ============================================================
// Main kernel: 128 CTAs x 256 threads, 2 anti-phase warp groups
// ============================================================
__global__ __launch_bounds__(256, 1)
void crowds_mma_kernel(const float* __restrict__ p, float* __restrict__ out) {
    extern __shared__ __align__(1024) uint8_t smem[];
    const uint32_t sb = smem_u32(smem);
    const float* biasS = (const float*)(smem + SM_BIAS);
    const float* psS   = (const float*)(smem + SM_P);

    const int tid = threadIdx.x, lane = tid & 31, warp = tid >> 5;
    const int grp = warp >> 2, wm = warp & 3, tid128 = tid & 127;
    const int rowbase = blockIdx.x * 128;
    const int barid = 1 + grp;

    // ---- prologue: X, bias (all threads); p transpose; unit 0 fetch ----
    {
        const uint8_t* gx = g_Xh + (size_t)blockIdx.x * 32768;
        #pragma unroll
        for (int i = 0; i < 8; i++) {
            int o = (tid + i * 256) * 16;
            cp16(sb + SM_XH + o, gx + o);
        }
        #pragma unroll
        for (int i = 0; i < 4; i++) {
            int o = (tid + i * 256) * 16;
            cp16(sb + SM_BIAS + o, (const uint8_t*)g_biasp + o);
        }
        asm volatile("cp.async.commit_group;");
        #pragma unroll
        for (int i = 0; i < 4; i++) {
            int ii = tid + i * 256;
            int row = ii >> 3, c = ii & 7;
            ((float*)(smem + SM_P))[c * 128 + row] = p[(size_t)(rowbase + row) * 8 + c];
        }
    }
    const uint32_t wbase = sb + SM_W + grp * 65536;
    float* stageG = (float*)(smem + SM_STAGE + grp * 16384);

    fetch_unit(wbase, /*slab=*/grp, /*h=*/0, tid128);   // group's unit 0
    asm volatile("cp.async.wait_group 0;");
    __syncthreads();

    // ---- hoist A fragments (slab-invariant) ----
    const int arow_base = wm * 32 + (lane & 7) + ((lane >> 3) & 1) * 8;
    uint32_t ah[8][2][4];
    #pragma unroll
    for (int ks8 = 0; ks8 < 8; ks8++) {
        const int xch = ks8 * 2 + (lane >> 4);
        #pragma unroll
        for (int mt = 0; mt < 2; mt++) {
            int row = arow_base + mt * 16;
            uint32_t aoff = (uint32_t)(row * 256 + ((xch ^ (row & 7)) << 4));
            LDSM4(ah[ks8][mt], sb + SM_XH + aoff);
        }
    }

    float acc[2][16][4];

    if (grp == 0) {
        // body: MMA(i) -> epilogue(i)
        for (int i = 0; i < 16; i++) {
            const int slab = 2 * (i >> 1), h = i & 1, ua = slab * 2 + h;
            BARG(barid);
            if (i + 1 < 16) {
                fetch_unit(wbase + ((i + 1) & 1) * 32768,
                           2 * ((i + 1) >> 1), (i + 1) & 1, tid128);
                asm volatile("cp.async.wait_group 1;");
            } else {
                asm volatile("cp.async.wait_group 0;");
            }
            mma_unit(acc, wbase + (i & 1) * 32768, ah, lane);
            epi_unit(acc, ua, h, biasS, psS, stageG, wm, lane);
            if (h == 1) {
                BARG(barid);
                store_slab(stageG, out, rowbase, slab, tid128);
            }
        }
    } else {
        // body: epilogue(i-1) -> MMA(i)   (anti-phase vs group 0)
        int pslab = 0, ph = 0, pua = 0;
        for (int i = 0; i < 16; i++) {
            const int slab = 2 * (i >> 1) + 1, h = i & 1, ua = slab * 2 + h;
            BARG(barid);
            if (i + 1 < 16)
                fetch_unit(wbase + ((i + 1) & 1) * 32768,
                           2 * ((i + 1) >> 1) + 1, (i + 1) & 1, tid128);
            if (i > 0) {
                epi_unit(acc, pua, ph, biasS, psS, stageG, wm, lane);
                if (ph == 1) {
                    BARG(barid);
                    store_slab(stageG, out, rowbase, pslab, tid128);
                }
            }
            if (i + 1 < 16) {
                asm volatile("cp.async.wait_group 1;");
            } else {
                asm volatile("cp.async.wait_group 0;");
            }
            mma_unit(acc, wbase + (i & 1) * 32768, ah, lane);
            pslab = slab; ph = h; pua = ua;
        }
        epi_unit(acc, pua, ph, biasS, psS, stageG, wm, lane);
        BARG(barid);
        store_slab(stageG, out, rowbase, pslab, tid128);
    }
}

// ============================================================
extern "C" void kernel_launch(void* const* d_in, const int* in_sizes, int n_in,
                              void* d_out, int out_size) {
    const float* x    = (const float*)d_in[0];
    const float* p    = (const float*)d_in[1];
    const float* W    = (const float*)d_in[2];
    const float* bias = (const float*)d_in[3];
    float* out = (float*)d_out;

    int B = in_sizes[0] / NF;                    // 16384

    prep_kernel<<<(B * 64) / 256, 256>>>(x, W, bias);

    cudaFuncSetAttribute(crowds_mma_kernel,
                         cudaFuncAttributeMaxDynamicSharedMemorySize, SM_TOT);
    crowds_mma_kernel<<<B / 128, 256, SM_TOT>>>(p, out);
}

// round 15
// speedup vs baseline: 1.0786x; 1.0786x over previous
#include <cuda_runtime.h>
#include <cuda_fp16.h>
#include <cstdint>

// ============================================================
// x(16384,128) f32, p(16384,8) f32, W(128,4096) f32, b(4096) f32
// logits[b,n] = sum_f x[b,f]*W[f,n],  n = c*512 + d*64 + r
// out[b, d*64+r] = sum_c p[b,c] * softmax_d(logits[b,c,:,r])
//
// R15: single-term fp16 mma.sync, columns permuted n'=r*64+c*8+d.
// No __syncthreads in main loop: 5-slot x 32KB W ring with
// mbarriers. FIXES vs R14: (1) cp.async.mbarrier.arrive.NOINC
// (default variant inflates expected count -> deadlock);
// (2) fetch units 2j+3,2j+4 at top of iter j, whose slots were
// consumed at iter j-1 -> empty-wait is a STALE rendezvous and
// warps can skew by ~1 iteration (epilogue overlaps other warps'
// HMMA). Direct float2 stores (out fits L2), no stage buffer.
// ============================================================

#define NF 128

// -------- device scratch --------
__device__ __align__(1024) uint8_t g_Wh[32u * 32768];   // unit u = (slab*2+kh)
__device__ __align__(1024) uint8_t g_Xh[128u * 32768];  // [rowblk][128r][16ch][16B]
__device__ __align__(16) float g_biasp[4096];

// -------- smem byte offsets --------
#define SM_XH    0                 // 32768
#define SM_W     32768             // 5 x 32768 ring
#define SM_BIAS  196608            // 16384
#define SM_P     212992            // 4096
#define SM_MB    217088            // full[0..4] @ +0, empty[0..4] @ +64
#define SM_TOT   217216

__device__ __forceinline__ uint32_t smem_u32(const void* p) {
    return (uint32_t)__cvta_generic_to_shared(p);
}
__device__ __forceinline__ void cp16(uint32_t dst, const void* src) {
    asm volatile("cp.async.cg.shared.global [%0], [%1], 16;" :: "r"(dst), "l"(src));
}
#define LDSM4(r, a) \
    asm volatile("ldmatrix.sync.aligned.m8n8.x4.shared.b16 {%0,%1,%2,%3}, [%4];" \
        : "=r"((r)[0]), "=r"((r)[1]), "=r"((r)[2]), "=r"((r)[3]) : "r"(a))

__device__ __forceinline__ void mma16816h(float* c, const uint32_t* a,
                                          uint32_t b0, uint32_t b1) {
    asm volatile(
        "mma.sync.aligned.m16n8k16.row.col.f32.f16.f16.f32 "
        "{%0,%1,%2,%3}, {%4,%5,%6,%7}, {%8,%9}, {%0,%1,%2,%3};"
        : "+f"(c[0]), "+f"(c[1]), "+f"(c[2]), "+f"(c[3])
        : "r"(a[0]), "r"(a[1]), "r"(a[2]), "r"(a[3]), "r"(b0), "r"(b1));
}
__device__ __forceinline__ uint32_t pack2h(float a, float b) {
    __half2 h;
    h.x = __float2half_rn(a);
    h.y = __float2half_rn(b);
    return *reinterpret_cast<uint32_t*>(&h);
}

// -------- mbarrier primitives --------
__device__ __forceinline__ void mb_init(uint32_t mb, uint32_t cnt) {
    asm volatile("mbarrier.init.shared.b64 [%0], %1;" :: "r"(mb), "r"(cnt) : "memory");
}
__device__ __forceinline__ void mb_arrive(uint32_t mb) {
    asm volatile("mbarrier.arrive.shared.b64 _, [%0];" :: "r"(mb) : "memory");
}
__device__ __forceinline__ void cp_arrive_noinc(uint32_t mb) {
    asm volatile("cp.async.mbarrier.arrive.noinc.shared::cta.b64 [%0];"
                 :: "r"(mb) : "memory");
}
__device__ __forceinline__ void mb_wait(uint32_t mb, uint32_t parity) {
    asm volatile(
        "{\n\t.reg .pred P;\n\t"
        "WL_%=:\n\t"
        "mbarrier.try_wait.parity.acquire.cta.shared::cta.b64 P, [%0], %1, 0x989680;\n\t"
        "@P bra WD_%=;\n\t"
        "bra WL_%=;\n\t"
        "WD_%=:\n\t}"
        :: "r"(mb), "r"(parity) : "memory");
}

// ============================================================
// Merged prep (unchanged, validated R10-R13)
// ============================================================
__global__ void prep_kernel(const float* __restrict__ X,
                            const float* __restrict__ W,
                            const float* __restrict__ bias) {
    int idx = blockIdx.x * 256 + threadIdx.x;

    if (idx < 4096) {
        int n = idx;
        int c = n >> 9, d = (n >> 6) & 7, r = n & 63;
        g_biasp[r * 64 + c * 8 + d] = bias[n];
    }

    if (idx < 64 * 4096) {
        int f2 = (idx >> 12) * 2;
        int n  = idx & 4095;
        float w0 = W[(size_t)f2 * 4096 + n];
        float w1 = W[(size_t)(f2 + 1) * 4096 + n];
        int c = n >> 9, d = (n >> 6) & 7, r = n & 63;
        int np = r * 64 + c * 8 + d;
        int slab = np >> 8, nl = np & 255;
        int kh = f2 >> 6, kl = f2 & 63;
        int ch = kl >> 3;
        uint32_t off = (uint32_t)(nl * 128 + (((ch ^ (nl & 7)) & 7) << 4) + (kl & 7) * 2);
        *(uint32_t*)(g_Wh + ((size_t)slab * 2 + kh) * 32768 + off) = pack2h(w0, w1);
    }

    {
        int row = idx >> 6;
        int k2  = (idx & 63) * 2;
        float2 v = *reinterpret_cast<const float2*>(X + (size_t)row * NF + k2);
        int blk = row >> 7, rl = row & 127;
        int ch = k2 >> 3;
        uint32_t off = (uint32_t)(rl * 256 + ((ch ^ (rl & 7)) << 4) + (k2 & 7) * 2);
        *(uint32_t*)(g_Xh + (size_t)blk * 32768 + off) = pack2h(v.x, v.y);
    }
}

// fetch one 32KB unit into its ring slot (all 256 threads; 8 cp16 each)
__device__ __forceinline__ void fetch_unit(uint32_t sb, int u, int tid) {
    int slot = u % 5;
    int fill = u / 5;
    if (fill >= 1)
        mb_wait(sb + SM_MB + 64 + slot * 8, (uint32_t)((fill - 1) & 1));
    const uint8_t* src = g_Wh + (size_t)u * 32768;
    uint32_t dst = sb + SM_W + slot * 32768;
    #pragma unroll
    for (int i = 0; i < 8; i++) {
        int o = (tid + i * 256) * 16;
        cp16(dst + o, src + o);
    }
    cp_arrive_noinc(sb + SM_MB + slot * 8);
}

// epilogue for one 16-col group pg, accumulating into of[][][]
__device__ __forceinline__ void epi_group(const float* a8, int pg, int j, int wn,
                                          int wm, int q, int rowq,
                                          const float* biasS, const float* psS,
                                          float (&of)[2][2][4]) {
    const int rb = pg >> 2;
    #pragma unroll
    for (int hf = 0; hf < 2; hf++) {
        const int c = (pg & 3) * 2 + hf;
        const int nb_abs = j * 256 + wn * 128 + pg * 16 + hf * 8;
        float2 bv = *(const float2*)&biasS[nb_abs + q * 2];
        #pragma unroll
        for (int mt = 0; mt < 2; mt++) {
            const int row0 = wm * 32 + mt * 16 + rowq;
            const float* a4 = a8 + (mt * 2 + hf) * 4;
            float e0 = __expf(a4[0] + bv.x);
            float e1 = __expf(a4[1] + bv.y);
            float e2 = __expf(a4[2] + bv.x);
            float e3 = __expf(a4[3] + bv.y);
            float s0 = e0 + e1, s1 = e2 + e3;
            s0 += __shfl_xor_sync(0xffffffffu, s0, 1);
            s0 += __shfl_xor_sync(0xffffffffu, s0, 2);
            s1 += __shfl_xor_sync(0xffffffffu, s1, 1);
            s1 += __shfl_xor_sync(0xffffffffu, s1, 2);
            float f0 = __fdividef(psS[c * 128 + row0], s0);
            float f1 = __fdividef(psS[c * 128 + row0 + 8], s1);
            of[mt][rb][0] = fmaf(e0, f0, of[mt][rb][0]);
            of[mt][rb][1] = fmaf(e1, f0, of[mt][rb][1]);
            of[mt][rb][2] = fmaf(e2, f1, of[mt][rb][2]);
            of[mt][rb][3] = fmaf(e3, f1, of[mt][rb][3]);
        }
    }
}

// ============================================================
// Main kernel: 128 CTAs x 256 threads, free-running warps
// ============================================================
__global__ __launch_bounds__(256, 1)
void crowds_mma_kernel(const float* __restrict__ p, float* __restrict__ out) {
    extern __shared__ __align__(1024) uint8_t smem[];
    const uint32_t sb = smem_u32(smem);
    const float* biasS = (const float*)(smem + SM_BIAS);
    const float* psS   = (const float*)(smem + SM_P);

    const int tid = threadIdx.x, lane = tid & 31, warp = tid >> 5;
    const int wm = warp >> 1, wn = warp & 1;    // warp tile 32 x 128
    const int rowbase = blockIdx.x * 128;

    // ---- init mbarriers ----
    if (tid == 0) {
        #pragma unroll
        for (int s = 0; s < 5; s++) {
            mb_init(sb + SM_MB + s * 8, 256);       // full: 256 noinc cp-arrives
            mb_init(sb + SM_MB + 64 + s * 8, 8);    // empty: 8 warp arrives
        }
    }
    __syncthreads();

    // ---- prologue: X + bias cp.async, units 0..2, p transpose ----
    {
        const uint8_t* gx = g_Xh + (size_t)blockIdx.x * 32768;
        #pragma unroll
        for (int i = 0; i < 8; i++) {
            int o = (tid + i * 256) * 16;
            cp16(sb + SM_XH + o, gx + o);
        }
        #pragma unroll
        for (int i = 0; i < 4; i++) {
            int o = (tid + i * 256) * 16;
            cp16(sb + SM_BIAS + o, (const uint8_t*)g_biasp + o);
        }
        #pragma unroll
        for (int u = 0; u < 3; u++)
            fetch_unit(sb, u, tid);     // unit0's arrive also covers X/bias
        #pragma unroll
        for (int i = 0; i < 4; i++) {
            int ii = tid + i * 256;
            int row = ii >> 3, c = ii & 7;
            ((float*)(smem + SM_P))[c * 128 + row] = p[(size_t)(rowbase + row) * 8 + c];
        }
    }
    __syncthreads();   // p visibility; last CTA-wide barrier

    // ---- hoist A fragments (full[0] implies all threads' X done) ----
    mb_wait(sb + SM_MB + 0, 0);
    const int arow_base = wm * 32 + (lane & 7) + ((lane >> 3) & 1) * 8;
    const int bn0 = wn * 128 + (lane & 7) + ((lane >> 4) << 3);
    const int q = lane & 3, rowq = lane >> 2;

    uint32_t ah[8][2][4];
    #pragma unroll
    for (int ks8 = 0; ks8 < 8; ks8++) {
        const int xch = ks8 * 2 + (lane >> 4);
        #pragma unroll
        for (int mt = 0; mt < 2; mt++) {
            int row = arow_base + mt * 16;
            uint32_t aoff = (uint32_t)(row * 256 + ((xch ^ (row & 7)) << 4));
            LDSM4(ah[ks8][mt], sb + SM_XH + aoff);
        }
    }

    float accb[2][2][2][4];   // [buf][mt][hf][4]
    float of[2][2][4];

    for (int j = 0; j < 16; j++) {
        // ---- top-of-body prefetch: units 2j+3, 2j+4 (slots consumed at j-1,
        //      so the empty-wait is stale -> warps may skew ~1 iteration) ----
        if (2 * j + 3 < 32) fetch_unit(sb, 2 * j + 3, tid);
        if (2 * j + 4 < 32) fetch_unit(sb, 2 * j + 4, tid);

        const int u0 = 2 * j, u1 = 2 * j + 1;
        const int s0 = u0 % 5, s1 = u1 % 5;
        mb_wait(sb + SM_MB + s0 * 8, (uint32_t)((u0 / 5) & 1));
        mb_wait(sb + SM_MB + s1 * 8, (uint32_t)((u1 / 5) & 1));
        const uint32_t wb0 = sb + SM_W + s0 * 32768;
        const uint32_t wb1 = sb + SM_W + s1 * 32768;

        #pragma unroll
        for (int mt = 0; mt < 2; mt++)
            #pragma unroll
            for (int rb = 0; rb < 2; rb++)
                #pragma unroll
                for (int e = 0; e < 4; e++) of[mt][rb][e] = 0.f;

        // ---- 8 groups of 16 cols; MMA(g) then epilogue(g-1) ----
        #pragma unroll
        for (int g = 0; g < 8; g++) {
            float* ag = &accb[g & 1][0][0][0];
            #pragma unroll
            for (int e = 0; e < 16; e++) ag[e] = 0.f;

            const int n = bn0 + g * 16;
            #pragma unroll
            for (int ks8 = 0; ks8 < 8; ks8++) {
                uint32_t bh[4];
                const int bch = (ks8 & 3) * 2 + ((lane >> 3) & 1);
                uint32_t boff = (uint32_t)(n * 128 + (((bch ^ (n & 7)) & 7) << 4));
                LDSM4(bh, (ks8 < 4 ? wb0 : wb1) + boff);
                #pragma unroll
                for (int mt = 0; mt < 2; mt++)
                    #pragma unroll
                    for (int hf = 0; hf < 2; hf++)
                        mma16816h(&accb[g & 1][mt][hf][0],
                                  ah[ks8][mt], bh[hf * 2], bh[hf * 2 + 1]);
            }
            if (g > 0)
                epi_group(&accb[(g - 1) & 1][0][0][0], g - 1, j, wn, wm, q, rowq,
                          biasS, psS, of);
        }

        // all LDSM reads of slots s0/s1 done -> release them
        __syncwarp();
        if (lane == 0) {
            mb_arrive(sb + SM_MB + 64 + s0 * 8);
            mb_arrive(sb + SM_MB + 64 + s1 * 8);
        }

        // last group epilogue (overlaps other warps' HMMA)
        epi_group(&accb[1][0][0][0], 7, j, wn, wm, q, rowq, biasS, psS, of);

        // ---- direct float2 stores (out is L2-resident; sectors merge) ----
        #pragma unroll
        for (int mt = 0; mt < 2; mt++) {
            const int rA = rowbase + wm * 32 + mt * 16 + rowq;
            float* b0 = out + (size_t)rA * 512 + (2 * q) * 64 + j * 4 + wn * 2;
            *(float2*)(b0)                = make_float2(of[mt][0][0], of[mt][1][0]);
            *(float2*)(b0 + 64)           = make_float2(of[mt][0][1], of[mt][1][1]);
            *(float2*)(b0 + 8 * 512)      = make_float2(of[mt][0][2], of[mt][1][2]);
            *(float2*)(b0 + 8 * 512 + 64) = make_float2(of[mt][0][3], of[mt][1][3]);
        }
    }
}

// ============================================================
extern "C" void kernel_launch(void* const* d_in, const int* in_sizes, int n_in,
                              void* d_out, int out_size) {
    const float* x    = (const float*)d_in[0];
    const float* p    = (const float*)d_in[1];
    const float* W    = (const float*)d_in[2];
    const float* bias = (const float*)d_in[3];
    float* out = (float*)d_out;

    int B = in_sizes[0] / NF;                    // 16384

    prep_kernel<<<(B * 64) / 256, 256>>>(x, W, bias);

    cudaFuncSetAttribute(crowds_mma_kernel,
                         cudaFuncAttributeMaxDynamicSharedMemorySize, SM_TOT);
    crowds_mma_kernel<<<B / 128, 256, SM_TOT>>>(p, out);
}